// round 1
// baseline (speedup 1.0000x reference)
#include <cuda_runtime.h>
#include <cuda_bf16.h>
#include <cstddef>

// ---------------- problem constants ----------------
#define BB   1024
#define CIN  256
#define HH   512
#define TT   32
#define EE   512
#define NEC  8192
#define HT   (HH*TT)          // 16384
#define RECON_N (BB*CIN*TT)   // 8388608

// ---------------- scratch (static device memory; no allocs) ----------------
__device__ float g_bufA[(size_t)BB*HH*TT];
__device__ float g_bufB[(size_t)BB*HH*TT];
__device__ float g_z  [(size_t)BB*EE];
__device__ float g_zq [(size_t)BB*EE];
__device__ float g_dot[(size_t)BB*NEC];
__device__ float g_cn [NEC];
__device__ float g_wc [(size_t)HH*HH*3];
__device__ float g_lp [BB];

// =====================================================================
// Conv1d (K=3, pad=1, stride 1) as tiled GEMM over channels.
// in: (B, C, 32)  w: (O, C, 3)  bias: (O)  out: (B, O, 32)
// Block: 256 thr, tile 128 o x 32 t per batch, C chunked by 16.
// =====================================================================
__global__ __launch_bounds__(256) void conv1d_k(
    const float* __restrict__ in, const float* __restrict__ w,
    const float* __restrict__ bias, float* __restrict__ out,
    int C, int O, int relu)
{
    __shared__ float xs[16*34];     // [c][tpos] tpos = t+1, halo zeros
    __shared__ float ws[48*129];    // [(c*3+k)][o] padded stride 129

    const int b   = blockIdx.x;
    const int o0  = blockIdx.y * 128;
    const int tid = threadIdx.x;
    const int tx  = tid & 7;        // t = 4*tx + i
    const int ty  = tid >> 3;       // o = o0 + 4*ty + j

    float acc[4][4];
    #pragma unroll
    for (int i = 0; i < 4; i++)
        #pragma unroll
        for (int j = 0; j < 4; j++) acc[i][j] = 0.f;

    const float* inb = in + (size_t)b * C * TT;

    for (int c0 = 0; c0 < C; c0 += 16) {
        // load x tile 16 x 34 (with halo)
        for (int i = tid; i < 16*34; i += 256) {
            int c = i / 34, tp = i % 34, t = tp - 1;
            xs[i] = (t >= 0 && t < TT) ? inb[(size_t)(c0 + c)*TT + t] : 0.f;
        }
        // load w tile: 128 o x (16 c x 3 k)
        for (int i = tid; i < 128*48; i += 256) {
            int o = i / 48, j = i % 48;                 // j = c*3 + k
            ws[j*129 + o] = w[(size_t)(o0 + o)*C*3 + (size_t)c0*3 + j];
        }
        __syncthreads();

        #pragma unroll
        for (int c = 0; c < 16; c++) {
            float xv[6];
            #pragma unroll
            for (int d = 0; d < 6; d++) xv[d] = xs[c*34 + 4*tx + d];
            #pragma unroll
            for (int k = 0; k < 3; k++) {
                float wv[4];
                #pragma unroll
                for (int j = 0; j < 4; j++) wv[j] = ws[(c*3 + k)*129 + ty*4 + j];
                #pragma unroll
                for (int j = 0; j < 4; j++)
                    #pragma unroll
                    for (int i = 0; i < 4; i++)
                        acc[i][j] += wv[j] * xv[i + k];
            }
        }
        __syncthreads();
    }

    float* outb = out + (size_t)b * O * TT;
    #pragma unroll
    for (int j = 0; j < 4; j++) {
        int o = o0 + ty*4 + j;
        float bv = bias[o];
        #pragma unroll
        for (int i = 0; i < 4; i++) {
            float v = acc[i][j] + bv;
            if (relu) v = fmaxf(v, 0.f);
            outb[(size_t)o*TT + 4*tx + i] = v;
        }
    }
}

// =====================================================================
// NT GEMM: C[m,n] = sum_k A[m*K+k] * B[n*K+k] (+bias[n]) (opt relu)
// 64x64 tile, K chunk 16, 256 threads, 4x4 per thread.
// =====================================================================
__global__ __launch_bounds__(256) void gemm_nt(
    const float* __restrict__ A, const float* __restrict__ Bm,
    const float* __restrict__ bias, float* __restrict__ C,
    int M, int N, int K, int relu)
{
    __shared__ float As[16][68];
    __shared__ float Bs[16][68];

    const int n0  = blockIdx.x * 64;
    const int m0  = blockIdx.y * 64;
    const int tid = threadIdx.x;
    const int tx  = tid & 15;       // n: 4 each
    const int ty  = tid >> 4;       // m: 4 each
    const int lr  = tid >> 2;       // load row 0..63
    const int lk  = (tid & 3) * 4;  // k offset

    float acc[4][4];
    #pragma unroll
    for (int i = 0; i < 4; i++)
        #pragma unroll
        for (int j = 0; j < 4; j++) acc[i][j] = 0.f;

    for (int k0 = 0; k0 < K; k0 += 16) {
        float4 av = *(const float4*)&A [(size_t)(m0 + lr)*K + k0 + lk];
        float4 bv = *(const float4*)&Bm[(size_t)(n0 + lr)*K + k0 + lk];
        As[lk+0][lr] = av.x; As[lk+1][lr] = av.y; As[lk+2][lr] = av.z; As[lk+3][lr] = av.w;
        Bs[lk+0][lr] = bv.x; Bs[lk+1][lr] = bv.y; Bs[lk+2][lr] = bv.z; Bs[lk+3][lr] = bv.w;
        __syncthreads();

        #pragma unroll
        for (int kk = 0; kk < 16; kk++) {
            float4 a = *(const float4*)&As[kk][ty*4];
            float4 b = *(const float4*)&Bs[kk][tx*4];
            acc[0][0] += a.x*b.x; acc[0][1] += a.x*b.y; acc[0][2] += a.x*b.z; acc[0][3] += a.x*b.w;
            acc[1][0] += a.y*b.x; acc[1][1] += a.y*b.y; acc[1][2] += a.y*b.z; acc[1][3] += a.y*b.w;
            acc[2][0] += a.z*b.x; acc[2][1] += a.z*b.y; acc[2][2] += a.z*b.z; acc[2][3] += a.z*b.w;
            acc[3][0] += a.w*b.x; acc[3][1] += a.w*b.y; acc[3][2] += a.w*b.z; acc[3][3] += a.w*b.w;
        }
        __syncthreads();
    }

    float bvs[4];
    #pragma unroll
    for (int j = 0; j < 4; j++) bvs[j] = bias ? bias[n0 + tx*4 + j] : 0.f;

    #pragma unroll
    for (int i = 0; i < 4; i++) {
        float4 v;
        v.x = acc[i][0] + bvs[0];
        v.y = acc[i][1] + bvs[1];
        v.z = acc[i][2] + bvs[2];
        v.w = acc[i][3] + bvs[3];
        if (relu) {
            v.x = fmaxf(v.x, 0.f); v.y = fmaxf(v.y, 0.f);
            v.z = fmaxf(v.z, 0.f); v.w = fmaxf(v.w, 0.f);
        }
        *(float4*)&C[(size_t)(m0 + ty*4 + i)*N + n0 + tx*4] = v;
    }
}

// =====================================================================
// codebook row norms: cn[n] = sum_e cb[n,e]^2     (one warp per n)
// =====================================================================
__global__ __launch_bounds__(256) void cnorm_k(const float* __restrict__ cb,
                                               float* __restrict__ cn)
{
    int n    = blockIdx.x * 8 + (threadIdx.x >> 5);
    int lane = threadIdx.x & 31;
    const float* r = cb + (size_t)n * EE;
    float s = 0.f;
    for (int e = lane; e < EE; e += 32) { float v = r[e]; s += v*v; }
    #pragma unroll
    for (int o = 16; o; o >>= 1) s += __shfl_down_sync(0xffffffffu, s, o);
    if (lane == 0) cn[n] = s;
}

// =====================================================================
// VQ: per-row argmin of (zn + cn[n]) - 2*dot  (mimics reference rounding,
// first-index tie-break), then gather z_q row + loss partial.
// =====================================================================
__global__ __launch_bounds__(256) void vq_k(
    const float* __restrict__ z, const float* __restrict__ dot,
    const float* __restrict__ cn, const float* __restrict__ cb,
    float* __restrict__ zq, float* __restrict__ lp)
{
    __shared__ float sv[256];
    __shared__ int   si[256];
    __shared__ float s_zn;
    const int b = blockIdx.x, tid = threadIdx.x;
    const float* zb = z + (size_t)b * EE;

    // ||z_b||^2 (deterministic block reduce)
    float zn = 0.f;
    for (int e = tid; e < EE; e += 256) { float v = zb[e]; zn += v*v; }
    sv[tid] = zn; __syncthreads();
    for (int s = 128; s > 0; s >>= 1) { if (tid < s) sv[tid] += sv[tid+s]; __syncthreads(); }
    if (tid == 0) s_zn = sv[0];
    __syncthreads();
    zn = s_zn;
    __syncthreads();

    // argmin with first-min tie break
    const float* db = dot + (size_t)b * NEC;
    float best = 3.4e38f; int bi = 0x7fffffff;
    for (int n = tid; n < NEC; n += 256) {
        float dval = (zn + cn[n]) - 2.0f * db[n];
        if (dval < best || (dval == best && n < bi)) { best = dval; bi = n; }
    }
    sv[tid] = best; si[tid] = bi; __syncthreads();
    for (int s = 128; s > 0; s >>= 1) {
        if (tid < s) {
            float v2 = sv[tid+s]; int i2 = si[tid+s];
            if (v2 < sv[tid] || (v2 == sv[tid] && i2 < si[tid])) { sv[tid] = v2; si[tid] = i2; }
        }
        __syncthreads();
    }
    const int idx = si[0];
    __syncthreads();

    // gather + loss partial
    const float* cbr = cb + (size_t)idx * EE;
    float ls = 0.f;
    for (int e = tid; e < EE; e += 256) {
        float q = cbr[e];
        zq[(size_t)b*EE + e] = q;
        float d = q - zb[e];
        ls += d * d;
    }
    sv[tid] = ls; __syncthreads();
    for (int s = 128; s > 0; s >>= 1) { if (tid < s) sv[tid] += sv[tid+s]; __syncthreads(); }
    if (tid == 0) lp[b] = sv[0];
}

__global__ __launch_bounds__(256) void loss_final_k(const float* __restrict__ lp,
                                                    float* __restrict__ outLoss)
{
    __shared__ float sm[256];
    int tid = threadIdx.x;
    float s = 0.f;
    #pragma unroll
    for (int i = 0; i < 4; i++) s += lp[tid + i*256];
    sm[tid] = s; __syncthreads();
    for (int st = 128; st > 0; st >>= 1) { if (tid < st) sm[tid] += sm[tid+st]; __syncthreads(); }
    if (tid == 0) *outLoss = sm[0] * 1.25f / ((float)BB * (float)EE);
}

// ConvTranspose weight -> equivalent conv weight: wc[o][c][k] = w[c][o][2-k]
__global__ __launch_bounds__(256) void wtrans_k(const float* __restrict__ w,
                                                float* __restrict__ wc, int I, int O)
{
    int total = I * O * 3;
    for (int i = blockIdx.x*blockDim.x + threadIdx.x; i < total; i += gridDim.x*blockDim.x) {
        int o = i / (I*3), r = i % (I*3), c = r/3, k = r%3;
        wc[i] = w[(size_t)c*O*3 + (size_t)o*3 + (2 - k)];
    }
}

// =====================================================================
extern "C" void kernel_launch(void* const* d_in, const int* in_sizes, int n_in,
                              void* d_out, int out_size)
{
    const float* x   = (const float*)d_in[0];
    const float* ew1 = (const float*)d_in[1];  const float* eb1 = (const float*)d_in[2];
    const float* ew2 = (const float*)d_in[3];  const float* eb2 = (const float*)d_in[4];
    const float* ew3 = (const float*)d_in[5];  const float* eb3 = (const float*)d_in[6];
    const float* ew4 = (const float*)d_in[7];  const float* eb4 = (const float*)d_in[8];
    const float* efw = (const float*)d_in[9];  const float* efb = (const float*)d_in[10];
    const float* cb  = (const float*)d_in[11];
    const float* dfw = (const float*)d_in[12]; const float* dfb = (const float*)d_in[13];
    const float* dw4 = (const float*)d_in[14]; const float* db4 = (const float*)d_in[15];
    const float* dw3 = (const float*)d_in[16]; const float* db3 = (const float*)d_in[17];
    const float* dw2 = (const float*)d_in[18]; const float* db2 = (const float*)d_in[19];
    const float* dw1 = (const float*)d_in[20]; const float* db1 = (const float*)d_in[21];
    float* out = (float*)d_out;

    float *bufA, *bufB, *z, *zq, *dot, *cn, *wc, *lp;
    cudaGetSymbolAddress((void**)&bufA, g_bufA);
    cudaGetSymbolAddress((void**)&bufB, g_bufB);
    cudaGetSymbolAddress((void**)&z,    g_z);
    cudaGetSymbolAddress((void**)&zq,   g_zq);
    cudaGetSymbolAddress((void**)&dot,  g_dot);
    cudaGetSymbolAddress((void**)&cn,   g_cn);
    cudaGetSymbolAddress((void**)&wc,   g_wc);
    cudaGetSymbolAddress((void**)&lp,   g_lp);

    dim3 cg4(BB, HH/128);   // 512-out conv grid
    dim3 cg2(BB, CIN/128);  // 256-out conv grid

    // ---- encoder ----
    conv1d_k<<<cg4, 256>>>(x,    ew1, eb1, bufA, CIN, HH, 1);
    conv1d_k<<<cg4, 256>>>(bufA, ew2, eb2, bufB, HH,  HH, 1);
    conv1d_k<<<cg4, 256>>>(bufB, ew3, eb3, bufA, HH,  HH, 1);
    conv1d_k<<<cg4, 256>>>(bufA, ew4, eb4, bufB, HH,  HH, 1);
    gemm_nt<<<dim3(EE/64, BB/64), 256>>>(bufB, efw, efb, z, BB, EE, HT, 0);

    // ---- VQ ----
    cnorm_k<<<NEC/8, 256>>>(cb, cn);
    gemm_nt<<<dim3(NEC/64, BB/64), 256>>>(z, cb, nullptr, dot, BB, NEC, EE, 0);
    vq_k<<<BB, 256>>>(z, dot, cn, cb, zq, lp);

    // ---- decoder ----
    gemm_nt<<<dim3(HT/64, BB/64), 256>>>(zq, dfw, dfb, bufA, BB, HT, EE, 0);
    wtrans_k<<<256, 256>>>(dw4, wc, HH, HH);
    conv1d_k<<<cg4, 256>>>(bufA, wc, db4, bufB, HH, HH, 1);
    wtrans_k<<<256, 256>>>(dw3, wc, HH, HH);
    conv1d_k<<<cg4, 256>>>(bufB, wc, db3, bufA, HH, HH, 1);
    wtrans_k<<<256, 256>>>(dw2, wc, HH, HH);
    conv1d_k<<<cg4, 256>>>(bufA, wc, db2, bufB, HH, HH, 1);
    wtrans_k<<<256, 256>>>(dw1, wc, HH, CIN);      // (512, 256, 3) -> (256, 512, 3)
    conv1d_k<<<cg2, 256>>>(bufB, wc, db1, out, HH, CIN, 0);

    // ---- loss ----
    if (out_size >= RECON_N + 1)
        loss_final_k<<<1, 256>>>(lp, out + RECON_N);
}

// round 2
// speedup vs baseline: 1.6373x; 1.6373x over previous
#include <cuda_runtime.h>
#include <cuda_bf16.h>
#include <cstddef>

// ---------------- problem constants ----------------
#define BB   1024
#define CIN  256
#define HH   512
#define TT   32
#define EE   512
#define NEC  8192
#define HT   (HH*TT)          // 16384
#define RECON_N (BB*CIN*TT)   // 8388608

// ---------------- scratch (static device memory; no allocs) ----------------
__device__ float g_bufA[(size_t)BB*HH*TT];
__device__ float g_bufB[(size_t)BB*HH*TT];
__device__ float g_z  [(size_t)BB*EE];
__device__ float g_zq [(size_t)BB*EE];
__device__ float g_dot[(size_t)BB*NEC];
__device__ float g_cn [NEC];
__device__ float g_wc [(size_t)HH*HH*3];
__device__ float g_lp [BB];

// =====================================================================
// Conv1d (K=3, pad=1, stride 1) as tiled GEMM over channels.
// in: (B, C, 32)  w: (O, C, 3)  bias: (O)  out: (B, O, 32)
// Block: 256 thr, tile 128 o x 32 t per batch, C chunked by 16.
// =====================================================================
__global__ __launch_bounds__(256) void conv1d_k(
    const float* __restrict__ in, const float* __restrict__ w,
    const float* __restrict__ bias, float* __restrict__ out,
    int C, int O, int relu)
{
    __shared__ float xs[16*34];     // [c][tpos] tpos = t+1, halo zeros
    __shared__ float ws[48*129];    // [(c*3+k)][o] padded stride 129

    const int b   = blockIdx.x;
    const int o0  = blockIdx.y * 128;
    const int tid = threadIdx.x;
    const int tx  = tid & 7;        // t = 4*tx + i
    const int ty  = tid >> 3;       // o = o0 + 4*ty + j

    float acc[4][4];
    #pragma unroll
    for (int i = 0; i < 4; i++)
        #pragma unroll
        for (int j = 0; j < 4; j++) acc[i][j] = 0.f;

    const float* inb = in + (size_t)b * C * TT;

    for (int c0 = 0; c0 < C; c0 += 16) {
        // load x tile 16 x 34 (with halo)
        for (int i = tid; i < 16*34; i += 256) {
            int c = i / 34, tp = i % 34, t = tp - 1;
            xs[i] = (t >= 0 && t < TT) ? inb[(size_t)(c0 + c)*TT + t] : 0.f;
        }
        // load w tile: 128 o x (16 c x 3 k)
        for (int i = tid; i < 128*48; i += 256) {
            int o = i / 48, j = i % 48;                 // j = c*3 + k
            ws[j*129 + o] = w[(size_t)(o0 + o)*C*3 + (size_t)c0*3 + j];
        }
        __syncthreads();

        #pragma unroll
        for (int c = 0; c < 16; c++) {
            float xv[6];
            #pragma unroll
            for (int d = 0; d < 6; d++) xv[d] = xs[c*34 + 4*tx + d];
            #pragma unroll
            for (int k = 0; k < 3; k++) {
                float wv[4];
                #pragma unroll
                for (int j = 0; j < 4; j++) wv[j] = ws[(c*3 + k)*129 + ty*4 + j];
                #pragma unroll
                for (int j = 0; j < 4; j++)
                    #pragma unroll
                    for (int i = 0; i < 4; i++)
                        acc[i][j] += wv[j] * xv[i + k];
            }
        }
        __syncthreads();
    }

    float* outb = out + (size_t)b * O * TT;
    #pragma unroll
    for (int j = 0; j < 4; j++) {
        int o = o0 + ty*4 + j;
        float bv = bias[o];
        #pragma unroll
        for (int i = 0; i < 4; i++) {
            float v = acc[i][j] + bv;
            if (relu) v = fmaxf(v, 0.f);
            outb[(size_t)o*TT + 4*tx + i] = v;
        }
    }
}

// =====================================================================
// NT GEMM: C[m,n] = sum_k A[m*K+k] * B[n*K+k] (+bias[n]) (opt relu)
// 64x64 tile, K chunk 16, 256 threads, 4x4 per thread.
// =====================================================================
__global__ __launch_bounds__(256) void gemm_nt(
    const float* __restrict__ A, const float* __restrict__ Bm,
    const float* __restrict__ bias, float* __restrict__ C,
    int M, int N, int K, int relu)
{
    __shared__ float As[16][68];
    __shared__ float Bs[16][68];

    const int n0  = blockIdx.x * 64;
    const int m0  = blockIdx.y * 64;
    const int tid = threadIdx.x;
    const int tx  = tid & 15;       // n: 4 each
    const int ty  = tid >> 4;       // m: 4 each
    const int lr  = tid >> 2;       // load row 0..63
    const int lk  = (tid & 3) * 4;  // k offset

    float acc[4][4];
    #pragma unroll
    for (int i = 0; i < 4; i++)
        #pragma unroll
        for (int j = 0; j < 4; j++) acc[i][j] = 0.f;

    for (int k0 = 0; k0 < K; k0 += 16) {
        float4 av = *(const float4*)&A [(size_t)(m0 + lr)*K + k0 + lk];
        float4 bv = *(const float4*)&Bm[(size_t)(n0 + lr)*K + k0 + lk];
        As[lk+0][lr] = av.x; As[lk+1][lr] = av.y; As[lk+2][lr] = av.z; As[lk+3][lr] = av.w;
        Bs[lk+0][lr] = bv.x; Bs[lk+1][lr] = bv.y; Bs[lk+2][lr] = bv.z; Bs[lk+3][lr] = bv.w;
        __syncthreads();

        #pragma unroll
        for (int kk = 0; kk < 16; kk++) {
            float4 a = *(const float4*)&As[kk][ty*4];
            float4 b = *(const float4*)&Bs[kk][tx*4];
            acc[0][0] += a.x*b.x; acc[0][1] += a.x*b.y; acc[0][2] += a.x*b.z; acc[0][3] += a.x*b.w;
            acc[1][0] += a.y*b.x; acc[1][1] += a.y*b.y; acc[1][2] += a.y*b.z; acc[1][3] += a.y*b.w;
            acc[2][0] += a.z*b.x; acc[2][1] += a.z*b.y; acc[2][2] += a.z*b.z; acc[2][3] += a.z*b.w;
            acc[3][0] += a.w*b.x; acc[3][1] += a.w*b.y; acc[3][2] += a.w*b.z; acc[3][3] += a.w*b.w;
        }
        __syncthreads();
    }

    float bvs[4];
    #pragma unroll
    for (int j = 0; j < 4; j++) bvs[j] = bias ? bias[n0 + tx*4 + j] : 0.f;

    #pragma unroll
    for (int i = 0; i < 4; i++) {
        float4 v;
        v.x = acc[i][0] + bvs[0];
        v.y = acc[i][1] + bvs[1];
        v.z = acc[i][2] + bvs[2];
        v.w = acc[i][3] + bvs[3];
        if (relu) {
            v.x = fmaxf(v.x, 0.f); v.y = fmaxf(v.y, 0.f);
            v.z = fmaxf(v.z, 0.f); v.w = fmaxf(v.w, 0.f);
        }
        *(float4*)&C[(size_t)(m0 + ty*4 + i)*N + n0 + tx*4] = v;
    }
}

// =====================================================================
// codebook row norms: cn[n] = sum_e cb[n,e]^2     (one warp per n)
// =====================================================================
__global__ __launch_bounds__(256) void cnorm_k(const float* __restrict__ cb,
                                               float* __restrict__ cn)
{
    int n    = blockIdx.x * 8 + (threadIdx.x >> 5);
    int lane = threadIdx.x & 31;
    const float* r = cb + (size_t)n * EE;
    float s = 0.f;
    for (int e = lane; e < EE; e += 32) { float v = r[e]; s += v*v; }
    #pragma unroll
    for (int o = 16; o; o >>= 1) s += __shfl_down_sync(0xffffffffu, s, o);
    if (lane == 0) cn[n] = s;
}

// =====================================================================
// VQ: per-row argmin of (zn + cn[n]) - 2*dot  (mimics reference rounding,
// first-index tie-break), then gather z_q row + loss partial.
// =====================================================================
__global__ __launch_bounds__(256) void vq_k(
    const float* __restrict__ z, const float* __restrict__ dot,
    const float* __restrict__ cn, const float* __restrict__ cb,
    float* __restrict__ zq, float* __restrict__ lp)
{
    __shared__ float sv[256];
    __shared__ int   si[256];
    __shared__ float s_zn;
    const int b = blockIdx.x, tid = threadIdx.x;
    const float* zb = z + (size_t)b * EE;

    // ||z_b||^2 (deterministic block reduce)
    float zn = 0.f;
    for (int e = tid; e < EE; e += 256) { float v = zb[e]; zn += v*v; }
    sv[tid] = zn; __syncthreads();
    for (int s = 128; s > 0; s >>= 1) { if (tid < s) sv[tid] += sv[tid+s]; __syncthreads(); }
    if (tid == 0) s_zn = sv[0];
    __syncthreads();
    zn = s_zn;
    __syncthreads();

    // argmin with first-min tie break
    const float* db = dot + (size_t)b * NEC;
    float best = 3.4e38f; int bi = 0x7fffffff;
    for (int n = tid; n < NEC; n += 256) {
        float dval = (zn + cn[n]) - 2.0f * db[n];
        if (dval < best || (dval == best && n < bi)) { best = dval; bi = n; }
    }
    sv[tid] = best; si[tid] = bi; __syncthreads();
    for (int s = 128; s > 0; s >>= 1) {
        if (tid < s) {
            float v2 = sv[tid+s]; int i2 = si[tid+s];
            if (v2 < sv[tid] || (v2 == sv[tid] && i2 < si[tid])) { sv[tid] = v2; si[tid] = i2; }
        }
        __syncthreads();
    }
    const int idx = si[0];
    __syncthreads();

    // gather + loss partial
    const float* cbr = cb + (size_t)idx * EE;
    float ls = 0.f;
    for (int e = tid; e < EE; e += 256) {
        float q = cbr[e];
        zq[(size_t)b*EE + e] = q;
        float d = q - zb[e];
        ls += d * d;
    }
    sv[tid] = ls; __syncthreads();
    for (int s = 128; s > 0; s >>= 1) { if (tid < s) sv[tid] += sv[tid+s]; __syncthreads(); }
    if (tid == 0) lp[b] = sv[0];
}

__global__ __launch_bounds__(256) void loss_final_k(const float* __restrict__ lp,
                                                    float* __restrict__ outLoss)
{
    __shared__ float sm[256];
    int tid = threadIdx.x;
    float s = 0.f;
    #pragma unroll
    for (int i = 0; i < 4; i++) s += lp[tid + i*256];
    sm[tid] = s; __syncthreads();
    for (int st = 128; st > 0; st >>= 1) { if (tid < st) sm[tid] += sm[tid+st]; __syncthreads(); }
    if (tid == 0) *outLoss = sm[0] * 1.25f / ((float)BB * (float)EE);
}

// ConvTranspose weight -> equivalent conv weight: wc[o][c][k] = w[c][o][2-k]
__global__ __launch_bounds__(256) void wtrans_k(const float* __restrict__ w,
                                                float* __restrict__ wc, int I, int O)
{
    int total = I * O * 3;
    for (int i = blockIdx.x*blockDim.x + threadIdx.x; i < total; i += gridDim.x*blockDim.x) {
        int o = i / (I*3), r = i % (I*3), c = r/3, k = r%3;
        wc[i] = w[(size_t)c*O*3 + (size_t)o*3 + (2 - k)];
    }
}

// =====================================================================
extern "C" void kernel_launch(void* const* d_in, const int* in_sizes, int n_in,
                              void* d_out, int out_size)
{
    const float* x   = (const float*)d_in[0];
    const float* ew1 = (const float*)d_in[1];  const float* eb1 = (const float*)d_in[2];
    const float* ew2 = (const float*)d_in[3];  const float* eb2 = (const float*)d_in[4];
    const float* ew3 = (const float*)d_in[5];  const float* eb3 = (const float*)d_in[6];
    const float* ew4 = (const float*)d_in[7];  const float* eb4 = (const float*)d_in[8];
    const float* efw = (const float*)d_in[9];  const float* efb = (const float*)d_in[10];
    const float* cb  = (const float*)d_in[11];
    const float* dfw = (const float*)d_in[12]; const float* dfb = (const float*)d_in[13];
    const float* dw4 = (const float*)d_in[14]; const float* db4 = (const float*)d_in[15];
    const float* dw3 = (const float*)d_in[16]; const float* db3 = (const float*)d_in[17];
    const float* dw2 = (const float*)d_in[18]; const float* db2 = (const float*)d_in[19];
    const float* dw1 = (const float*)d_in[20]; const float* db1 = (const float*)d_in[21];
    float* out = (float*)d_out;

    float *bufA, *bufB, *z, *zq, *dot, *cn, *wc, *lp;
    cudaGetSymbolAddress((void**)&bufA, g_bufA);
    cudaGetSymbolAddress((void**)&bufB, g_bufB);
    cudaGetSymbolAddress((void**)&z,    g_z);
    cudaGetSymbolAddress((void**)&zq,   g_zq);
    cudaGetSymbolAddress((void**)&dot,  g_dot);
    cudaGetSymbolAddress((void**)&cn,   g_cn);
    cudaGetSymbolAddress((void**)&wc,   g_wc);
    cudaGetSymbolAddress((void**)&lp,   g_lp);

    dim3 cg4(BB, HH/128);   // 512-out conv grid
    dim3 cg2(BB, CIN/128);  // 256-out conv grid

    // ---- encoder ----
    conv1d_k<<<cg4, 256>>>(x,    ew1, eb1, bufA, CIN, HH, 1);
    conv1d_k<<<cg4, 256>>>(bufA, ew2, eb2, bufB, HH,  HH, 1);
    conv1d_k<<<cg4, 256>>>(bufB, ew3, eb3, bufA, HH,  HH, 1);
    conv1d_k<<<cg4, 256>>>(bufA, ew4, eb4, bufB, HH,  HH, 1);
    gemm_nt<<<dim3(EE/64, BB/64), 256>>>(bufB, efw, efb, z, BB, EE, HT, 0);

    // ---- VQ ----
    cnorm_k<<<NEC/8, 256>>>(cb, cn);
    gemm_nt<<<dim3(NEC/64, BB/64), 256>>>(z, cb, nullptr, dot, BB, NEC, EE, 0);
    vq_k<<<BB, 256>>>(z, dot, cn, cb, zq, lp);

    // ---- decoder ----
    gemm_nt<<<dim3(HT/64, BB/64), 256>>>(zq, dfw, dfb, bufA, BB, HT, EE, 0);
    wtrans_k<<<256, 256>>>(dw4, wc, HH, HH);
    conv1d_k<<<cg4, 256>>>(bufA, wc, db4, bufB, HH, HH, 1);
    wtrans_k<<<256, 256>>>(dw3, wc, HH, HH);
    conv1d_k<<<cg4, 256>>>(bufB, wc, db3, bufA, HH, HH, 1);
    wtrans_k<<<256, 256>>>(dw2, wc, HH, HH);
    conv1d_k<<<cg4, 256>>>(bufA, wc, db2, bufB, HH, HH, 1);
    wtrans_k<<<256, 256>>>(dw1, wc, HH, CIN);      // (512, 256, 3) -> (256, 512, 3)
    conv1d_k<<<cg2, 256>>>(bufB, wc, db1, out, HH, CIN, 0);

    // ---- loss ----
    if (out_size >= RECON_N + 1)
        loss_final_k<<<1, 256>>>(lp, out + RECON_N);
}

// round 4
// speedup vs baseline: 6.0306x; 3.6832x over previous
#include <cuda_runtime.h>
#include <cuda_bf16.h>
#include <cstdint>
#include <cstddef>

typedef __nv_bfloat16 bf16;

#define BB   1024
#define CIN  256
#define HH   512
#define TT   32
#define EE   512
#define NEC  8192
#define RECON_N (BB*CIN*TT)
#define NNC  (BB*TT)          // 32768 GEMM-N for convs

#define GS 81920              // dynamic smem: 2 buffers x 4 tiles x 10240B

// ---------------- static device scratch ----------------
__device__ bf16 g_actAh[(size_t)NNC*HH], g_actAl[(size_t)NNC*HH];
__device__ bf16 g_actBh[(size_t)NNC*HH], g_actBl[(size_t)NNC*HH];
__device__ bf16 g_wA1h[512*768],   g_wA1l[512*768];
__device__ bf16 g_wA2h[512*1536],  g_wA2l[512*1536];
__device__ bf16 g_wA3h[512*1536],  g_wA3l[512*1536];
__device__ bf16 g_wA4h[512*1536],  g_wA4l[512*1536];
__device__ bf16 g_wD4h[512*1536],  g_wD4l[512*1536];
__device__ bf16 g_wD3h[512*1536],  g_wD3l[512*1536];
__device__ bf16 g_wD2h[512*1536],  g_wD2l[512*1536];
__device__ bf16 g_wD1h[256*1536],  g_wD1l[256*1536];
__device__ bf16 g_wFEh[(size_t)512*16384], g_wFEl[(size_t)512*16384];
__device__ bf16 g_wFDh[(size_t)16384*512], g_wFDl[(size_t)16384*512];
__device__ bf16 g_cbh[(size_t)NEC*EE],     g_cbl[(size_t)NEC*EE];
__device__ float g_dfb2[16384];
__device__ float g_part[(size_t)8*BB*EE];
__device__ float g_z[(size_t)BB*EE];
__device__ bf16  g_zh[(size_t)BB*EE],  g_zl[(size_t)BB*EE];
__device__ bf16  g_zqh[(size_t)BB*EE], g_zql[(size_t)BB*EE];
__device__ float g_dot[(size_t)BB*NEC];
__device__ float g_cn[NEC];
__device__ float g_lp[BB];

// ---------------- helpers ----------------
__device__ __forceinline__ void split2(float v, bf16& h, bf16& l){
    h = __float2bfloat16_rn(v);
    l = __float2bfloat16_rn(v - __bfloat162float(h));
}
__device__ __forceinline__ void mma_bf16(float* c, const uint32_t* a, const uint32_t* b){
    asm volatile("mma.sync.aligned.m16n8k16.row.col.f32.bf16.bf16.f32 "
        "{%0,%1,%2,%3}, {%4,%5,%6,%7}, {%8,%9}, {%0,%1,%2,%3};"
        : "+f"(c[0]), "+f"(c[1]), "+f"(c[2]), "+f"(c[3])
        : "r"(a[0]), "r"(a[1]), "r"(a[2]), "r"(a[3]), "r"(b[0]), "r"(b[1]));
}
template<int N> __device__ __forceinline__ void cp_wait(){
    asm volatile("cp.async.wait_group %0;" :: "n"(N) : "memory");
}
__device__ __forceinline__ void cp_commit(){
    asm volatile("cp.async.commit_group;" ::: "memory");
}

// stage one 128x32 x4-tile chunk into buffer `buf` via cp.async (16B, zfill for halo)
__device__ __forceinline__ void stage_chunk(
    char* smemBase, int buf,
    const bf16* __restrict__ Ah, const bf16* __restrict__ Al,
    const bf16* __restrict__ Bh, const bf16* __restrict__ Bl,
    int m0, int n0, int k0, int K, int convC, int tid)
{
    uint32_t sb = (uint32_t)__cvta_generic_to_shared(smemBase) + buf*40960;
    #pragma unroll
    for (int half = 0; half < 2; half++){
        const bf16* src = half ? Al : Ah;
        uint32_t tb = sb + half*10240;
        #pragma unroll
        for (int it = 0; it < 2; it++){
            int task = tid + it*256;
            int r = task >> 2, seg = task & 3;
            const void* g = src + (size_t)(m0 + r)*K + k0 + seg*8;
            asm volatile("cp.async.cg.shared.global [%0], [%1], 16;"
                :: "r"(tb + r*80 + seg*16), "l"(g));
        }
    }
    #pragma unroll
    for (int half = 0; half < 2; half++){
        const bf16* src = half ? Bl : Bh;
        uint32_t tb = sb + 20480 + half*10240;
        #pragma unroll
        for (int it = 0; it < 2; it++){
            int task = tid + it*256;
            int r = task >> 2, seg = task & 3;
            int n = n0 + r;
            const bf16* g; int sz = 16;
            if (convC){
                int t = n & 31, ks2 = k0 / convC, kr = k0 - ks2*convC;
                if ((unsigned)(t + ks2 - 1) < 32u)
                    g = src + (size_t)(n + ks2 - 1)*convC + kr + seg*8;
                else { g = src; sz = 0; }
            } else {
                g = src + (size_t)n*K + k0 + seg*8;
            }
            asm volatile("cp.async.cg.shared.global [%0], [%1], 16, %2;"
                :: "r"(tb + r*80 + seg*16), "l"((const void*)g), "r"(sz));
        }
    }
}

// =====================================================================
// split-bf16 NT GEMM via mma.sync (HMMA). D[m,n] = sum_k A[m,k]*B[n,k],
// A~Ah+Al, B~Bh+Bl, 3 terms hh+hl+lh, fp32 accum.
// grid = (Ntot/128, Mtot/128, zsplit). convC: implicit im2col on B rows.
// fmode 1 -> outF[n*ldc+m]; fmode 2 -> outF[(n>>5)*Mtot*32 + m*32 + (n&31)];
// outH/outL -> split act at [n*Mtot+m]. zsplit>1: fp32 partials.
// =====================================================================
__global__ void __launch_bounds__(256) gemm_mma(
    const bf16* __restrict__ Ah, const bf16* __restrict__ Al,
    const bf16* __restrict__ Bh, const bf16* __restrict__ Bl,
    const float* __restrict__ bias, float* __restrict__ outF,
    bf16* __restrict__ outH, bf16* __restrict__ outL,
    float* __restrict__ partBase,
    int Mtot, int K, int kseg, int convC, int fmode, int ldc, int relu)
{
    extern __shared__ char smem[];
    const int tid  = threadIdx.x;
    const int lane = tid & 31, wid = tid >> 5;
    const int wm = wid >> 2, wn = wid & 3;     // 2 x 4 warp grid
    const int m0 = blockIdx.y * 128;
    const int n0 = blockIdx.x * 128;
    const int kb = blockIdx.z * kseg;
    const int NC = kseg / 32;

    float acc[4][4][4];
    #pragma unroll
    for (int i = 0; i < 4; i++)
        #pragma unroll
        for (int j = 0; j < 4; j++)
            #pragma unroll
            for (int r = 0; r < 4; r++) acc[i][j][r] = 0.f;

    stage_chunk(smem, 0, Ah, Al, Bh, Bl, m0, n0, kb, K, convC, tid);
    cp_commit();
    if (NC > 1){
        stage_chunk(smem, 1, Ah, Al, Bh, Bl, m0, n0, kb + 32, K, convC, tid);
        cp_commit();
    }

    const uint32_t* sw = (const uint32_t*)smem;

    for (int ci = 0; ci < NC; ci++){
        if (ci + 1 < NC) cp_wait<1>(); else cp_wait<0>();
        __syncthreads();

        const uint32_t* sb = sw + (ci & 1) * 10240;
        const uint32_t* sAh = sb;
        const uint32_t* sAl = sb + 2560;
        const uint32_t* sBh = sb + 5120;
        const uint32_t* sBl = sb + 7680;

        #pragma unroll
        for (int s = 0; s < 2; s++){
            const int kwo = s*8;
            uint32_t ah[4][4], al[4][4], bh[4][2], bl[4][2];
            #pragma unroll
            for (int i = 0; i < 4; i++){
                int wb = (wm*64 + i*16 + (lane >> 2))*20 + kwo + (lane & 3);
                ah[i][0] = sAh[wb];       ah[i][1] = sAh[wb + 160];
                ah[i][2] = sAh[wb + 4];   ah[i][3] = sAh[wb + 164];
                al[i][0] = sAl[wb];       al[i][1] = sAl[wb + 160];
                al[i][2] = sAl[wb + 4];   al[i][3] = sAl[wb + 164];
            }
            #pragma unroll
            for (int j = 0; j < 4; j++){
                int wb = (wn*32 + j*8 + (lane >> 2))*20 + kwo + (lane & 3);
                bh[j][0] = sBh[wb];  bh[j][1] = sBh[wb + 4];
                bl[j][0] = sBl[wb];  bl[j][1] = sBl[wb + 4];
            }
            #pragma unroll
            for (int i = 0; i < 4; i++)
                #pragma unroll
                for (int j = 0; j < 4; j++){
                    mma_bf16(acc[i][j], ah[i], bh[j]);
                    mma_bf16(acc[i][j], ah[i], bl[j]);
                    mma_bf16(acc[i][j], al[i], bh[j]);
                }
        }
        __syncthreads();
        if (ci + 2 < NC){
            stage_chunk(smem, ci & 1, Ah, Al, Bh, Bl, m0, n0,
                        kb + (ci + 2)*32, K, convC, tid);
            cp_commit();
        }
    }

    // ---- epilogue ----
    const bool dosplit = (gridDim.z > 1);
    const int nTot = gridDim.x * 128;
    float* fO = outF; int fm = fmode; int lld = ldc;
    bf16 *oH = outH, *oL = outL;
    if (dosplit){
        fO = partBase + (size_t)blockIdx.z * Mtot * nTot;
        fm = 1; lld = Mtot; oH = nullptr; oL = nullptr;
    }
    #pragma unroll
    for (int i = 0; i < 4; i++){
        const int mA = m0 + wm*64 + i*16 + (lane >> 2);
        const int mB = mA + 8;
        const float bvA = (!dosplit && bias) ? bias[mA] : 0.f;
        const float bvB = (!dosplit && bias) ? bias[mB] : 0.f;
        #pragma unroll
        for (int j = 0; j < 4; j++){
            const int nb = n0 + wn*32 + j*8 + (lane & 3)*2;
            float v[4];
            v[0] = acc[i][j][0] + bvA;  v[1] = acc[i][j][1] + bvA;
            v[2] = acc[i][j][2] + bvB;  v[3] = acc[i][j][3] + bvB;
            if (relu){
                #pragma unroll
                for (int r = 0; r < 4; r++) v[r] = fmaxf(v[r], 0.f);
            }
            const int mm[4] = {mA, mA, mB, mB};
            const int nn[4] = {nb, nb + 1, nb, nb + 1};
            #pragma unroll
            for (int r = 0; r < 4; r++){
                const int m = mm[r], n = nn[r];
                if (fm == 1)
                    fO[(size_t)n * lld + m] = v[r];
                else if (fm == 2)
                    fO[(size_t)(n >> 5) * ((size_t)Mtot * 32) + (size_t)m * 32 + (n & 31)] = v[r];
                if (oH){
                    bf16 h = __float2bfloat16_rn(v[r]);
                    oH[(size_t)n * Mtot + m] = h;
                    oL[(size_t)n * Mtot + m] = __float2bfloat16_rn(v[r] - __bfloat162float(h));
                }
            }
        }
    }
}

// ---------------- transforms ----------------
__global__ __launch_bounds__(256) void wconv_k(const float* __restrict__ w,
    bf16* __restrict__ h, bf16* __restrict__ l, int O, int C, int isT)
{
    int total = O * C * 3;
    for (int i = blockIdx.x*blockDim.x + threadIdx.x; i < total; i += gridDim.x*blockDim.x){
        int o = i / (C*3), r = i % (C*3), c = r / 3, k = r % 3;
        float v = isT ? w[((size_t)c*O + o)*3 + (2 - k)] : w[i];
        size_t d = (size_t)o*(3*C) + k*C + c;
        bf16 hh, ll; split2(v, hh, ll); h[d] = hh; l[d] = ll;
    }
}
__global__ __launch_bounds__(256) void wfe_k(const float* __restrict__ w,
    bf16* __restrict__ h, bf16* __restrict__ l)
{
    size_t total = (size_t)512*16384;
    for (size_t i = blockIdx.x*(size_t)blockDim.x + threadIdx.x; i < total;
         i += (size_t)gridDim.x*blockDim.x){
        int e = (int)(i >> 14), fp = (int)(i & 16383);
        int t = fp >> 9, c = fp & 511;
        float v = w[(size_t)e*16384 + c*32 + t];
        bf16 hh, ll; split2(v, hh, ll); h[i] = hh; l[i] = ll;
    }
}
__global__ __launch_bounds__(256) void wfd_k(const float* __restrict__ w,
    bf16* __restrict__ h, bf16* __restrict__ l)
{
    size_t total = (size_t)16384*512;
    for (size_t i = blockIdx.x*(size_t)blockDim.x + threadIdx.x; i < total;
         i += (size_t)gridDim.x*blockDim.x){
        int fp = (int)(i >> 9), e = (int)(i & 511);
        int t = fp >> 9, c = fp & 511;
        float v = w[((size_t)(c*32 + t))*512 + e];
        bf16 hh, ll; split2(v, hh, ll); h[i] = hh; l[i] = ll;
    }
}
__global__ __launch_bounds__(256) void dfb2_k(const float* __restrict__ b,
    float* __restrict__ b2)
{
    int i = blockIdx.x*blockDim.x + threadIdx.x;
    int t = i >> 9, c = i & 511;
    b2[i] = b[c*32 + t];
}
__global__ __launch_bounds__(256) void plainsplit_k(const float* __restrict__ s,
    bf16* __restrict__ h, bf16* __restrict__ l, size_t n)
{
    for (size_t i = blockIdx.x*(size_t)blockDim.x + threadIdx.x; i < n;
         i += (size_t)gridDim.x*blockDim.x){
        bf16 hh, ll; split2(s[i], hh, ll); h[i] = hh; l[i] = ll;
    }
}
__global__ __launch_bounds__(256) void xsplit_k(const float* __restrict__ x,
    bf16* __restrict__ h, bf16* __restrict__ l)
{
    size_t total = (size_t)BB*CIN*TT;
    for (size_t i = blockIdx.x*(size_t)blockDim.x + threadIdx.x; i < total;
         i += (size_t)gridDim.x*blockDim.x){
        int b = (int)(i >> 13), r = (int)(i & 8191);
        int c = r >> 5, t = r & 31;
        size_t d = (size_t)(b*32 + t)*256 + c;
        bf16 hh, ll; split2(x[i], hh, ll); h[d] = hh; l[d] = ll;
    }
}
__global__ __launch_bounds__(256) void reducez_k(const float* __restrict__ part,
    const float* __restrict__ efb, float* __restrict__ z,
    bf16* __restrict__ zh, bf16* __restrict__ zl)
{
    int i = blockIdx.x*blockDim.x + threadIdx.x;   // 524288
    int e = i & 511;
    float s = 0.f;
    #pragma unroll
    for (int k = 0; k < 8; k++) s += part[(size_t)k*524288 + i];
    s += efb[e];
    z[i] = s;
    bf16 hh, ll; split2(s, hh, ll); zh[i] = hh; zl[i] = ll;
}
__global__ __launch_bounds__(256) void cnorm_k(const float* __restrict__ cb,
                                               float* __restrict__ cn)
{
    int n = blockIdx.x*8 + (threadIdx.x >> 5);
    int lane = threadIdx.x & 31;
    const float* r = cb + (size_t)n*EE;
    float s = 0.f;
    for (int e = lane; e < EE; e += 32){ float v = r[e]; s += v*v; }
    #pragma unroll
    for (int o = 16; o; o >>= 1) s += __shfl_down_sync(0xffffffffu, s, o);
    if (lane == 0) cn[n] = s;
}
__global__ __launch_bounds__(256) void vq_k(
    const float* __restrict__ z, const float* __restrict__ dot,
    const float* __restrict__ cn, const float* __restrict__ cb,
    bf16* __restrict__ zqh, bf16* __restrict__ zql, float* __restrict__ lp)
{
    __shared__ float sv[256];
    __shared__ int   si[256];
    __shared__ float s_zn;
    const int b = blockIdx.x, tid = threadIdx.x;
    const float* zb = z + (size_t)b*EE;

    float zn = 0.f;
    for (int e = tid; e < EE; e += 256){ float v = zb[e]; zn += v*v; }
    sv[tid] = zn; __syncthreads();
    for (int s = 128; s > 0; s >>= 1){ if (tid < s) sv[tid] += sv[tid+s]; __syncthreads(); }
    if (tid == 0) s_zn = sv[0];
    __syncthreads();
    zn = s_zn; __syncthreads();

    const float* db = dot + (size_t)b*NEC;
    float best = 3.4e38f; int bi = 0x7fffffff;
    for (int n = tid; n < NEC; n += 256){
        float dv = (zn + cn[n]) - 2.0f * db[n];
        if (dv < best || (dv == best && n < bi)){ best = dv; bi = n; }
    }
    sv[tid] = best; si[tid] = bi; __syncthreads();
    for (int s = 128; s > 0; s >>= 1){
        if (tid < s){
            float v2 = sv[tid+s]; int i2 = si[tid+s];
            if (v2 < sv[tid] || (v2 == sv[tid] && i2 < si[tid])){ sv[tid] = v2; si[tid] = i2; }
        }
        __syncthreads();
    }
    const int idx = si[0];
    __syncthreads();

    const float* cbr = cb + (size_t)idx*EE;
    float ls = 0.f;
    for (int e = tid; e < EE; e += 256){
        float q = cbr[e];
        bf16 hh, ll; split2(q, hh, ll);
        zqh[(size_t)b*EE + e] = hh; zql[(size_t)b*EE + e] = ll;
        float d = q - zb[e]; ls += d*d;
    }
    sv[tid] = ls; __syncthreads();
    for (int s = 128; s > 0; s >>= 1){ if (tid < s) sv[tid] += sv[tid+s]; __syncthreads(); }
    if (tid == 0) lp[b] = sv[0];
}
__global__ __launch_bounds__(256) void loss_final_k(const float* __restrict__ lp,
                                                    float* __restrict__ outLoss)
{
    __shared__ float sm[256];
    int tid = threadIdx.x;
    float s = 0.f;
    #pragma unroll
    for (int i = 0; i < 4; i++) s += lp[tid + i*256];
    sm[tid] = s; __syncthreads();
    for (int st = 128; st > 0; st >>= 1){ if (tid < st) sm[tid] += sm[tid+st]; __syncthreads(); }
    if (tid == 0) *outLoss = sm[0] * 1.25f / ((float)BB * (float)EE);
}

// =====================================================================
#define SYM(p, s) do{ void* _t; cudaGetSymbolAddress(&_t, s); p = (decltype(p))_t; }while(0)

extern "C" void kernel_launch(void* const* d_in, const int* in_sizes, int n_in,
                              void* d_out, int out_size)
{
    const float* x   = (const float*)d_in[0];
    const float* ew1 = (const float*)d_in[1];  const float* eb1 = (const float*)d_in[2];
    const float* ew2 = (const float*)d_in[3];  const float* eb2 = (const float*)d_in[4];
    const float* ew3 = (const float*)d_in[5];  const float* eb3 = (const float*)d_in[6];
    const float* ew4 = (const float*)d_in[7];  const float* eb4 = (const float*)d_in[8];
    const float* efw = (const float*)d_in[9];  const float* efb = (const float*)d_in[10];
    const float* cb  = (const float*)d_in[11];
    const float* dfw = (const float*)d_in[12]; const float* dfb = (const float*)d_in[13];
    const float* dw4 = (const float*)d_in[14]; const float* db4 = (const float*)d_in[15];
    const float* dw3 = (const float*)d_in[16]; const float* db3 = (const float*)d_in[17];
    const float* dw2 = (const float*)d_in[18]; const float* db2 = (const float*)d_in[19];
    const float* dw1 = (const float*)d_in[20]; const float* db1 = (const float*)d_in[21];
    float* out = (float*)d_out;

    bf16 *aAh,*aAl,*aBh,*aBl;
    bf16 *w1h,*w1l,*w2h,*w2l,*w3h,*w3l,*w4h,*w4l;
    bf16 *d4h,*d4l,*d3h,*d3l,*d2h,*d2l,*d1h,*d1l;
    bf16 *feh,*fel,*fdh,*fdl,*cbh,*cbl,*zh,*zl,*zqh,*zql;
    float *part,*z,*dot,*cn,*lp,*dfb2;
    SYM(aAh,g_actAh); SYM(aAl,g_actAl); SYM(aBh,g_actBh); SYM(aBl,g_actBl);
    SYM(w1h,g_wA1h); SYM(w1l,g_wA1l); SYM(w2h,g_wA2h); SYM(w2l,g_wA2l);
    SYM(w3h,g_wA3h); SYM(w3l,g_wA3l); SYM(w4h,g_wA4h); SYM(w4l,g_wA4l);
    SYM(d4h,g_wD4h); SYM(d4l,g_wD4l); SYM(d3h,g_wD3h); SYM(d3l,g_wD3l);
    SYM(d2h,g_wD2h); SYM(d2l,g_wD2l); SYM(d1h,g_wD1h); SYM(d1l,g_wD1l);
    SYM(feh,g_wFEh); SYM(fel,g_wFEl); SYM(fdh,g_wFDh); SYM(fdl,g_wFDl);
    SYM(cbh,g_cbh);  SYM(cbl,g_cbl);
    SYM(zh,g_zh); SYM(zl,g_zl); SYM(zqh,g_zqh); SYM(zql,g_zql);
    SYM(part,g_part); SYM(z,g_z); SYM(dot,g_dot); SYM(cn,g_cn); SYM(lp,g_lp);
    SYM(dfb2,g_dfb2);

    cudaFuncSetAttribute(gemm_mma, cudaFuncAttributeMaxDynamicSharedMemorySize, GS);

    // ---- transforms ----
    xsplit_k<<<1024, 256>>>(x, aAh, aAl);
    wconv_k<<<512, 256>>>(ew1, w1h, w1l, 512, 256, 0);
    wconv_k<<<512, 256>>>(ew2, w2h, w2l, 512, 512, 0);
    wconv_k<<<512, 256>>>(ew3, w3h, w3l, 512, 512, 0);
    wconv_k<<<512, 256>>>(ew4, w4h, w4l, 512, 512, 0);
    wfe_k<<<2048, 256>>>(efw, feh, fel);
    plainsplit_k<<<2048, 256>>>(cb, cbh, cbl, (size_t)NEC*EE);
    cnorm_k<<<NEC/8, 256>>>(cb, cn);
    wfd_k<<<2048, 256>>>(dfw, fdh, fdl);
    dfb2_k<<<64, 256>>>(dfb, dfb2);
    wconv_k<<<512, 256>>>(dw4, d4h, d4l, 512, 512, 1);
    wconv_k<<<512, 256>>>(dw3, d3h, d3l, 512, 512, 1);
    wconv_k<<<512, 256>>>(dw2, d2h, d2l, 512, 512, 1);
    wconv_k<<<512, 256>>>(dw1, d1h, d1l, 256, 512, 1);

    // ---- encoder convs ----
    gemm_mma<<<dim3(NNC/128, 4, 1), 256, GS>>>(w1h, w1l, aAh, aAl, eb1,
        nullptr, aBh, aBl, nullptr, 512, 768,  768,  256, 0, 0, 1);
    gemm_mma<<<dim3(NNC/128, 4, 1), 256, GS>>>(w2h, w2l, aBh, aBl, eb2,
        nullptr, aAh, aAl, nullptr, 512, 1536, 1536, 512, 0, 0, 1);
    gemm_mma<<<dim3(NNC/128, 4, 1), 256, GS>>>(w3h, w3l, aAh, aAl, eb3,
        nullptr, aBh, aBl, nullptr, 512, 1536, 1536, 512, 0, 0, 1);
    gemm_mma<<<dim3(NNC/128, 4, 1), 256, GS>>>(w4h, w4l, aBh, aBl, eb4,
        nullptr, aAh, aAl, nullptr, 512, 1536, 1536, 512, 0, 0, 1);

    // ---- encoder FC: M=512, N=1024, K=16384, split-K=8 ----
    gemm_mma<<<dim3(BB/128, 4, 8), 256, GS>>>(feh, fel, aAh, aAl, nullptr,
        nullptr, nullptr, nullptr, part, 512, 16384, 2048, 0, 0, 0, 0);
    reducez_k<<<2048, 256>>>(part, efb, z, zh, zl);

    // ---- VQ: dot = z @ cb^T ----
    gemm_mma<<<dim3(BB/128, NEC/128, 1), 256, GS>>>(cbh, cbl, zh, zl, nullptr,
        dot, nullptr, nullptr, nullptr, NEC, EE, EE, 0, 1, NEC, 0);
    vq_k<<<BB, 256>>>(z, dot, cn, cb, zqh, zql, lp);

    // ---- decoder FC: M=16384, N=1024, K=512 ----
    gemm_mma<<<dim3(BB/128, 16384/128, 1), 256, GS>>>(fdh, fdl, zqh, zql, dfb2,
        nullptr, aBh, aBl, nullptr, 16384, EE, EE, 0, 0, 0, 0);

    // ---- decoder convs ----
    gemm_mma<<<dim3(NNC/128, 4, 1), 256, GS>>>(d4h, d4l, aBh, aBl, db4,
        nullptr, aAh, aAl, nullptr, 512, 1536, 1536, 512, 0, 0, 1);
    gemm_mma<<<dim3(NNC/128, 4, 1), 256, GS>>>(d3h, d3l, aAh, aAl, db3,
        nullptr, aBh, aBl, nullptr, 512, 1536, 1536, 512, 0, 0, 1);
    gemm_mma<<<dim3(NNC/128, 4, 1), 256, GS>>>(d2h, d2l, aBh, aBl, db2,
        nullptr, aAh, aAl, nullptr, 512, 1536, 1536, 512, 0, 0, 1);
    gemm_mma<<<dim3(NNC/128, 2, 1), 256, GS>>>(d1h, d1l, aAh, aAl, db1,
        out, nullptr, nullptr, nullptr, 256, 1536, 1536, 512, 2, 0, 0);

    if (out_size >= RECON_N + 1)
        loss_final_k<<<1, 256>>>(lp, out + RECON_N);
}